// round 10
// baseline (speedup 1.0000x reference)
#include <cuda_runtime.h>
#include <math.h>

// B=4, T=2048, D=1024, H=16, HD=64, E=16 -> 64 active tokens total
#define SP  68   // iter tile stride (float4-aligned)
#define SPP 68   // GEMM tile stride (float4-aligned for f32x2 pairing)

// ---------------- scratch ----------------
__device__ float g_xn[64 * 1024];          // LN(x), token-major [tok*1024 + o]
__device__ float g_qkvp[24 * 64 * 1024];   // qkv split-K partials [proj*8+chunk][tok*1024+o]
__device__ float g_outp[8 * 64 * 1024];    // outproj partials [chunk][tok*1024+o]
__device__ float g_qc2[64 * 1024];         // qcur after iter1   [(b*16+h)*1024 + t*64+d]
__device__ float g_k2[64 * 1024];
__device__ float g_v2[64 * 1024];
__device__ float g_ai1[64 * 1024];
__device__ float g_aflat[64 * 1024];       // attn_out token-major [tok*1024 + h*64+d]
__device__ float g_diffpart[64];

// smem layout for iter kernels (floats)
#define WT_SZ   (64 * SP)
#define TILE_SZ (16 * SP)
#define OFF_WTQ 0
#define OFF_WTK (WT_SZ)
#define OFF_WTV (2 * WT_SZ)
#define OFF_QIN (3 * WT_SZ)
#define OFF_KIN (OFF_QIN + TILE_SZ)
#define OFF_VIN (OFF_KIN + TILE_SZ)
#define OFF_TQ  (OFF_VIN + TILE_SZ)
#define OFF_KLO (OFF_TQ + TILE_SZ)
#define OFF_VLO (OFF_KLO + TILE_SZ)
#define OFF_KSB (OFF_VLO + TILE_SZ)
#define OFF_PRB (OFF_KSB + TILE_SZ)
#define SMEM_ITER_FLOATS (OFF_PRB + 256)
#define SMEM_ITER_BYTES (SMEM_ITER_FLOATS * 4)

// ---------------- f32x2 packed helpers (Blackwell FFMA2) ----------------
__device__ __forceinline__ unsigned long long pk2(float lo, float hi) {
    unsigned long long r;
    asm("mov.b64 %0, {%1, %2};" : "=l"(r) : "f"(lo), "f"(hi));
    return r;
}
__device__ __forceinline__ void fma2(unsigned long long& d, unsigned long long a,
                                     unsigned long long b) {
    asm("fma.rn.f32x2 %0, %1, %2, %0;" : "+l"(d) : "l"(a), "l"(b));
}
__device__ __forceinline__ float up2sum(unsigned long long v) {
    float lo, hi;
    asm("mov.b64 {%0, %1}, %2;" : "=f"(lo), "=f"(hi) : "l"(v));
    return lo + hi;
}

// ---------------- K_fillln: out=bo everywhere (t<16 overwritten later) + LN ----------------
__global__ void __launch_bounds__(256) fillln_kernel(const float* __restrict__ bo,
                                                     const float* __restrict__ x,
                                                     const float* __restrict__ lna,
                                                     float4* __restrict__ out) {
    const int tid = threadIdx.x;
    const int bidx = blockIdx.x;
    out[bidx * 256 + tid] = __ldg(&((const float4*)bo)[tid]);

    if (bidx < 64) {
        const int b = bidx >> 4, t = bidx & 15;
        const int wid = tid >> 5, lane = tid & 31;
        const float4* xr = (const float4*)(x + (size_t)(b * 2048 + t) * 1024);
        __shared__ float wp[8];
        __shared__ float stat[2];

        float4 v = __ldg(&xr[tid]);
        float s = (v.x + v.y) + (v.z + v.w);
#pragma unroll
        for (int o = 16; o > 0; o >>= 1) s += __shfl_xor_sync(0xffffffffu, s, o);
        if (lane == 0) wp[wid] = s;
        __syncthreads();
        if (tid == 0) {
            float m = 0.f;
#pragma unroll
            for (int i = 0; i < 8; i++) m += wp[i];
            stat[0] = m * (1.0f / 1024.0f);
        }
        __syncthreads();
        float m = stat[0];
        float dx = v.x - m, dy = v.y - m, dz = v.z - m, dw = v.w - m;
        float q = fmaf(dx, dx, dy * dy) + fmaf(dz, dz, dw * dw);
#pragma unroll
        for (int o = 16; o > 0; o >>= 1) q += __shfl_xor_sync(0xffffffffu, q, o);
        if (lane == 0) wp[wid] = q;
        __syncthreads();
        if (tid == 0) {
            float vv = 0.f;
#pragma unroll
            for (int i = 0; i < 8; i++) vv += wp[i];
            stat[1] = rsqrtf(vv * (1.0f / 1024.0f) + 1e-5f);
        }
        __syncthreads();
        float inv = stat[1];
        float4 w = __ldg(&((const float4*)lna)[tid]);
        float4 r;
        r.x = dx * inv * w.x; r.y = dy * inv * w.y;
        r.z = dz * inv * w.z; r.w = dw * inv * w.w;
        ((float4*)g_xn)[bidx * 256 + tid] = r;
    }
}

// ---------------- K_proj: split-K GEMM partials with f32x2. grid (16,3,8) ----------------
__global__ void __launch_bounds__(256) proj_kernel(const float* __restrict__ Wq,
                                                   const float* __restrict__ Wk,
                                                   const float* __restrict__ Wv) {
    const int o0 = blockIdx.x * 64;
    const int proj = blockIdx.y;
    const int chunk = blockIdx.z;
    const float* W = (proj == 0) ? Wq : ((proj == 1) ? Wk : Wv);
    __shared__ float As[64][SPP];
    __shared__ float Ws[64][SPP];
    const int tid = threadIdx.x;
    const int tx = tid & 15, ty = tid >> 4;
    unsigned long long acc2[4][4];
#pragma unroll
    for (int i = 0; i < 4; i++)
#pragma unroll
        for (int j = 0; j < 4; j++) acc2[i][j] = 0ull;

#pragma unroll
    for (int kt = 0; kt < 2; kt++) {
        int k0 = chunk * 128 + kt * 64;
#pragma unroll
        for (int l = tid; l < 4096; l += 256) {
            int r = l >> 6, c = l & 63;
            As[r][c] = g_xn[r * 1024 + k0 + c];
            Ws[r][c] = __ldg(&W[(size_t)(o0 + r) * 1024 + k0 + c]);
        }
        __syncthreads();
#pragma unroll
        for (int kq = 0; kq < 16; kq++) {
            float4 a0 = *(const float4*)&As[ty * 4 + 0][kq * 4];
            float4 a1 = *(const float4*)&As[ty * 4 + 1][kq * 4];
            float4 a2 = *(const float4*)&As[ty * 4 + 2][kq * 4];
            float4 a3 = *(const float4*)&As[ty * 4 + 3][kq * 4];
            float4 w0 = *(const float4*)&Ws[tx * 4 + 0][kq * 4];
            float4 w1 = *(const float4*)&Ws[tx * 4 + 1][kq * 4];
            float4 w2 = *(const float4*)&Ws[tx * 4 + 2][kq * 4];
            float4 w3 = *(const float4*)&Ws[tx * 4 + 3][kq * 4];
            unsigned long long al[4] = {pk2(a0.x, a0.y), pk2(a1.x, a1.y),
                                        pk2(a2.x, a2.y), pk2(a3.x, a3.y)};
            unsigned long long ah[4] = {pk2(a0.z, a0.w), pk2(a1.z, a1.w),
                                        pk2(a2.z, a2.w), pk2(a3.z, a3.w)};
            unsigned long long wl[4] = {pk2(w0.x, w0.y), pk2(w1.x, w1.y),
                                        pk2(w2.x, w2.y), pk2(w3.x, w3.y)};
            unsigned long long wh[4] = {pk2(w0.z, w0.w), pk2(w1.z, w1.w),
                                        pk2(w2.z, w2.w), pk2(w3.z, w3.w)};
#pragma unroll
            for (int i = 0; i < 4; i++)
#pragma unroll
                for (int j = 0; j < 4; j++) {
                    fma2(acc2[i][j], al[i], wl[j]);
                    fma2(acc2[i][j], ah[i], wh[j]);
                }
        }
        __syncthreads();
    }

    float* dst = g_qkvp + (size_t)(proj * 8 + chunk) * 65536;
#pragma unroll
    for (int i = 0; i < 4; i++) {
        int tk = ty * 4 + i;
#pragma unroll
        for (int j = 0; j < 4; j++)
            dst[tk * 1024 + o0 + tx * 4 + j] = up2sum(acc2[i][j]);
    }
}

// ---------------- micro matmul: 128 threads, 8 outputs/thread (4 rows x 2 cols) ----------------
// Within a warp all lanes share the same input rows -> input LDS reads are broadcasts.
__device__ __forceinline__ void mm8(int tid_m, const float* Wt,
                                    const float* __restrict__ bias,
                                    const float* in, float* outb) {
    const int c = tid_m & 31;
    const int g = tid_m >> 5;   // 0..3 -> rows g, g+4, g+8, g+12
    const float4* r0 = (const float4*)(in + g * SP);
    const float4* r1 = (const float4*)(in + (g + 4) * SP);
    const float4* r2 = (const float4*)(in + (g + 8) * SP);
    const float4* r3 = (const float4*)(in + (g + 12) * SP);
    float acc[4][2];
#pragma unroll
    for (int i = 0; i < 4; i++) { acc[i][0] = 0.f; acc[i][1] = 0.f; }
#pragma unroll
    for (int jq = 0; jq < 16; jq++) {
        float4 x0 = r0[jq], x1 = r1[jq], x2 = r2[jq], x3 = r3[jq];
        float xv[4][4] = {{x0.x, x0.y, x0.z, x0.w}, {x1.x, x1.y, x1.z, x1.w},
                          {x2.x, x2.y, x2.z, x2.w}, {x3.x, x3.y, x3.z, x3.w}};
#pragma unroll
        for (int l = 0; l < 4; l++) {
            float wA = Wt[(jq * 4 + l) * SP + c];
            float wB = Wt[(jq * 4 + l) * SP + c + 32];
#pragma unroll
            for (int i = 0; i < 4; i++) {
                acc[i][0] = fmaf(xv[i][l], wA, acc[i][0]);
                acc[i][1] = fmaf(xv[i][l], wB, acc[i][1]);
            }
        }
    }
    float bA = __ldg(&bias[c]), bB = __ldg(&bias[c + 32]);
#pragma unroll
    for (int i = 0; i < 4; i++) {
        int row = g + 4 * i;
        outb[row * SP + c] = acc[i][0] + bA;
        outb[row * SP + c + 32] = acc[i][1] + bB;
    }
}

__device__ __forceinline__ void loadWt(const float* __restrict__ W, float* Wt, int tid) {
    for (int idx = tid; idx < 4096; idx += 512) {
        int d = idx >> 6, j = idx & 63;
        Wt[j * SP + d] = __ldg(&W[idx]);   // transposed: Wt[j][d]
    }
}

// One inner iteration for one (b,h): 512 threads. ai returned in registers.
__device__ __forceinline__ void small_iter512(int tid,
        const float* Wtq, const float* Wtk, const float* Wtv,
        const float* __restrict__ blq, const float* __restrict__ blk,
        const float* __restrict__ blv,
        const float* __restrict__ lnc, const float* __restrict__ lnd,
        float tscale,
        const float* qsrc, const float* ksrc, const float* vsrc,
        float* qd, float* kd, float* vd, float* ksb, float* probs,
        float& ai_lo, float& ai_hi) {
    // --- 3 concurrent micro-matmuls: warps 0-3 Q, 4-7 K, 8-11 V; warps 12-15 idle ---
    if (tid < 128)       mm8(tid,       Wtq, blq, qsrc, qd);
    else if (tid < 256)  mm8(tid - 128, Wtk, blk, ksrc, kd);
    else if (tid < 384)  mm8(tid - 256, Wtv, blv, vsrc, vd);
    __syncthreads();

    // --- LayerNorm(64): warps 0-7 -> q rows (in place), warps 8-15 -> k rows -> ksb ---
    {
        const int wid = tid >> 5, lane = tid & 31;
        const float* src = (wid < 8) ? qd : kd;
        float* dst = (wid < 8) ? qd : ksb;
        const float* lw = (wid < 8) ? lnc : lnd;
        const float sc = (wid < 8) ? tscale : 1.0f;
        const int row0 = (wid & 7) * 2;
#pragma unroll
        for (int rr = 0; rr < 2; rr++) {
            int row = row0 + rr;
            float v0 = src[row * SP + lane], v1 = src[row * SP + lane + 32];
            float s = v0 + v1;
#pragma unroll
            for (int o = 16; o > 0; o >>= 1) s += __shfl_xor_sync(0xffffffffu, s, o);
            float m = s * (1.0f / 64.0f);
            float d0 = v0 - m, d1 = v1 - m;
            float q = fmaf(d0, d0, d1 * d1);
#pragma unroll
            for (int o = 16; o > 0; o >>= 1) q += __shfl_xor_sync(0xffffffffu, q, o);
            float inv = rsqrtf(q * (1.0f / 64.0f) + 1e-5f) * sc;
            dst[row * SP + lane] = d0 * inv * __ldg(&lw[lane]);
            dst[row * SP + lane + 32] = d1 * inv * __ldg(&lw[lane + 32]);
        }
    }
    __syncthreads();

    // --- logits (16x16) * 1/8 ---
    if (tid < 256) {
        int t = tid >> 4, s_ = tid & 15;
        const float4* a4 = (const float4*)(qd + t * SP);
        const float4* k4 = (const float4*)(ksb + s_ * SP);
        float acc = 0.f;
#pragma unroll
        for (int jq = 0; jq < 16; jq++) {
            float4 a = a4[jq], k = k4[jq];
            acc = fmaf(a.x, k.x, acc); acc = fmaf(a.y, k.y, acc);
            acc = fmaf(a.z, k.z, acc); acc = fmaf(a.w, k.w, acc);
        }
        probs[tid] = acc * 0.125f;
    }
    __syncthreads();

    // --- softmax rows: one warp per row ---
    {
        const int wid = tid >> 5, lane = tid & 31;
        int s_ = lane & 15;
        float p = probs[wid * 16 + s_];
        float mx = p;
#pragma unroll
        for (int o = 8; o > 0; o >>= 1) mx = fmaxf(mx, __shfl_xor_sync(0xffffffffu, mx, o));
        float ex = __expf(p - mx);
        float sm = ex;
#pragma unroll
        for (int o = 8; o > 0; o >>= 1) sm += __shfl_xor_sync(0xffffffffu, sm, o);
        probs[wid * 16 + s_] = ex / sm;
    }
    __syncthreads();

    // --- ai = probs @ vl (2 outputs/thread, registers) ---
    {
        const int d = tid & 63, ts = tid >> 6;
        float a = 0.f, b = 0.f;
#pragma unroll
        for (int s_ = 0; s_ < 16; s_++) {
            float vv = vd[s_ * SP + d];
            a = fmaf(probs[ts * 16 + s_], vv, a);
            b = fmaf(probs[(ts + 8) * 16 + s_], vv, b);
        }
        ai_lo = a; ai_hi = b;
    }
    __syncthreads();
}

// ---------------- K_iter01: iterations 0 and 1 + diff partials ----------------
__global__ void __launch_bounds__(512) iter01_kernel(
        const float* __restrict__ Wlq, const float* __restrict__ blq,
        const float* __restrict__ Wlk, const float* __restrict__ blk,
        const float* __restrict__ Wlv, const float* __restrict__ blv,
        const float* __restrict__ lnc, const float* __restrict__ lnd,
        const float* __restrict__ temp,
        const float* __restrict__ bq, const float* __restrict__ bv) {
    extern __shared__ float smx[];
    float* Wtq = smx + OFF_WTQ; float* Wtk = smx + OFF_WTK; float* Wtv = smx + OFF_WTV;
    float* qin = smx + OFF_QIN; float* kin = smx + OFF_KIN; float* vin = smx + OFF_VIN;
    float* tqb = smx + OFF_TQ;  float* klo = smx + OFF_KLO; float* vlo = smx + OFF_VLO;
    float* ksb = smx + OFF_KSB; float* probs = smx + OFF_PRB;
    const int bx = blockIdx.x, tid = threadIdx.x;
    const int b = bx >> 4, h = bx & 15;

    loadWt(Wlq, Wtq, tid);
    loadWt(Wlk, Wtk, tid);
    loadWt(Wlv, Wtv, tid);

    // reduce qkv split-K partials (fixed order), apply scale/bias
    const float SC = 0.35355339059327373f;   // 64^-0.25
    for (int e = tid; e < 1024; e += 512) {
        int t = e >> 6, dd = e & 63;
        int o = h * 64 + dd;
        int g = (b * 16 + t) * 1024 + o;
        float qv = 0.f, kv = 0.f, vv = 0.f;
#pragma unroll
        for (int c = 0; c < 8; c++) {
            qv += __ldg(&g_qkvp[(size_t)c * 65536 + g]);
            kv += __ldg(&g_qkvp[(size_t)(8 + c) * 65536 + g]);
            vv += __ldg(&g_qkvp[(size_t)(16 + c) * 65536 + g]);
        }
        qin[t * SP + dd] = (qv + __ldg(&bq[o])) * SC;
        kin[t * SP + dd] = kv * SC;
        vin[t * SP + dd] = vv + __ldg(&bv[o]);
    }
    __syncthreads();

    const float temp0 = __ldg(temp);
    float t0 = temp0;
    float ts0 = (t0 != 1.0f && t0 > 0.0f) ? rsqrtf(t0) : 1.0f;
    float ai0_lo, ai0_hi;
    small_iter512(tid, Wtq, Wtk, Wtv, blq, blk, blv, lnc, lnd, ts0,
                  qin, kin, vin, tqb, klo, vlo, ksb, probs, ai0_lo, ai0_hi);

    const int d = tid & 63, ts = tid >> 6;
    qin[ts * SP + d] += ai0_lo;
    qin[(ts + 8) * SP + d] += ai0_hi;
    __syncthreads();

    float t1 = temp0 + 0.005f;
    float ts1 = (t1 != 1.0f && t1 > 0.0f) ? rsqrtf(t1) : 1.0f;
    float ai1_lo, ai1_hi;
    // inputs: qin (updated), klo/vlo (kl0/vl0); outputs: tqb, kin(kl1), vin(vl1)
    small_iter512(tid, Wtq, Wtk, Wtv, blq, blk, blv, lnc, lnd, ts1,
                  qin, klo, vlo, tqb, kin, vin, ksb, probs, ai1_lo, ai1_hi);

    const int base = bx * 1024;
    const int elo = ts * 64 + d, ehi = (ts + 8) * 64 + d;
    g_ai1[base + elo] = ai1_lo;
    g_ai1[base + ehi] = ai1_hi;
    g_qc2[base + elo] = qin[ts * SP + d] + ai1_lo;
    g_qc2[base + ehi] = qin[(ts + 8) * SP + d] + ai1_hi;
    g_k2[base + elo] = kin[ts * SP + d];
    g_k2[base + ehi] = kin[(ts + 8) * SP + d];
    g_v2[base + elo] = vin[ts * SP + d];
    g_v2[base + ehi] = vin[(ts + 8) * SP + d];

    float psum = fabsf(ai1_lo - ai0_lo) + fabsf(ai1_hi - ai0_hi);
#pragma unroll
    for (int o = 16; o > 0; o >>= 1) psum += __shfl_xor_sync(0xffffffffu, psum, o);
    const int wid = tid >> 5, lane = tid & 31;
    if (lane == 0) probs[wid] = psum;
    __syncthreads();
    if (tid == 0) {
        float s = 0.f;
#pragma unroll
        for (int i = 0; i < 16; i++) s += probs[i];   // fixed order
        g_diffpart[bx] = s;
    }
}

// ---------------- K_iter2: diff check + conditional iteration 2 ----------------
__global__ void __launch_bounds__(512) iter2_kernel(
        const float* __restrict__ Wlq, const float* __restrict__ blq,
        const float* __restrict__ Wlk, const float* __restrict__ blk,
        const float* __restrict__ Wlv, const float* __restrict__ blv,
        const float* __restrict__ lnc, const float* __restrict__ lnd,
        const float* __restrict__ temp, const float* __restrict__ thrp,
        const float* __restrict__ facp) {
    extern __shared__ float smx[];
    float* Wtq = smx + OFF_WTQ; float* Wtk = smx + OFF_WTK; float* Wtv = smx + OFF_WTV;
    float* qin = smx + OFF_QIN; float* kin = smx + OFF_KIN; float* vin = smx + OFF_VIN;
    float* tqb = smx + OFF_TQ;  float* klo = smx + OFF_KLO; float* vlo = smx + OFF_VLO;
    float* ksb = smx + OFF_KSB; float* probs = smx + OFF_PRB;
    const int bx = blockIdx.x, tid = threadIdx.x;
    const int b = bx >> 4, h = bx & 15;

    if (tid < 64) probs[tid] = g_diffpart[tid];
    __syncthreads();
    if (tid == 0) {
        float s = 0.f;
#pragma unroll
        for (int i = 0; i < 64; i++) s += probs[i];   // fixed order: deterministic
        float diff = s * (1.0f / 8388608.0f);         // mean over B*H*T*hd
        float th = __ldg(thrp), fa = __ldg(facp);
        probs[64] = (diff < th + fa * diff) ? 1.0f : 0.0f;
    }
    __syncthreads();
    bool done = (probs[64] != 0.0f);

    if (done) {
        for (int e = tid; e < 1024; e += 512) {
            int t = e >> 6, dd = e & 63;
            g_aflat[(b * 16 + t) * 1024 + h * 64 + dd] = g_ai1[bx * 1024 + e];
        }
        return;
    }
    __syncthreads();

    loadWt(Wlq, Wtq, tid);
    loadWt(Wlk, Wtk, tid);
    loadWt(Wlv, Wtv, tid);
    for (int e = tid; e < 1024; e += 512) {
        int t = e >> 6, dd = e & 63, idx = t * SP + dd;
        qin[idx] = g_qc2[bx * 1024 + e];
        kin[idx] = g_k2[bx * 1024 + e];
        vin[idx] = g_v2[bx * 1024 + e];
    }
    __syncthreads();

    float t2 = __ldg(temp) + 0.01f;
    float ts2 = (t2 != 1.0f && t2 > 0.0f) ? rsqrtf(t2) : 1.0f;
    float ai_lo, ai_hi;
    small_iter512(tid, Wtq, Wtk, Wtv, blq, blk, blv, lnc, lnd, ts2,
                  qin, kin, vin, tqb, klo, vlo, ksb, probs, ai_lo, ai_hi);

    const int d = tid & 63, ts = tid >> 6;
    g_aflat[(b * 16 + ts) * 1024 + h * 64 + d] = ai_lo;
    g_aflat[(b * 16 + ts + 8) * 1024 + h * 64 + d] = ai_hi;
}

// ---------------- K_outproj: split-K partials with f32x2. grid (16,8) ----------------
__global__ void __launch_bounds__(256) outproj_kernel(const float* __restrict__ Wo) {
    const int o0 = blockIdx.x * 64;
    const int chunk = blockIdx.y;
    __shared__ float As[64][SPP];
    __shared__ float Ws[64][SPP];
    const int tid = threadIdx.x;
    const int tx = tid & 15, ty = tid >> 4;
    unsigned long long acc2[4][4];
#pragma unroll
    for (int i = 0; i < 4; i++)
#pragma unroll
        for (int j = 0; j < 4; j++) acc2[i][j] = 0ull;

#pragma unroll
    for (int kt = 0; kt < 2; kt++) {
        int k0 = chunk * 128 + kt * 64;
#pragma unroll
        for (int l = tid; l < 4096; l += 256) {
            int r = l >> 6, c = l & 63;
            As[r][c] = g_aflat[r * 1024 + k0 + c];
            Ws[r][c] = __ldg(&Wo[(size_t)(o0 + r) * 1024 + k0 + c]);
        }
        __syncthreads();
#pragma unroll
        for (int kq = 0; kq < 16; kq++) {
            float4 a0 = *(const float4*)&As[ty * 4 + 0][kq * 4];
            float4 a1 = *(const float4*)&As[ty * 4 + 1][kq * 4];
            float4 a2 = *(const float4*)&As[ty * 4 + 2][kq * 4];
            float4 a3 = *(const float4*)&As[ty * 4 + 3][kq * 4];
            float4 w0 = *(const float4*)&Ws[tx * 4 + 0][kq * 4];
            float4 w1 = *(const float4*)&Ws[tx * 4 + 1][kq * 4];
            float4 w2 = *(const float4*)&Ws[tx * 4 + 2][kq * 4];
            float4 w3 = *(const float4*)&Ws[tx * 4 + 3][kq * 4];
            unsigned long long al[4] = {pk2(a0.x, a0.y), pk2(a1.x, a1.y),
                                        pk2(a2.x, a2.y), pk2(a3.x, a3.y)};
            unsigned long long ah[4] = {pk2(a0.z, a0.w), pk2(a1.z, a1.w),
                                        pk2(a2.z, a2.w), pk2(a3.z, a3.w)};
            unsigned long long wl[4] = {pk2(w0.x, w0.y), pk2(w1.x, w1.y),
                                        pk2(w2.x, w2.y), pk2(w3.x, w3.y)};
            unsigned long long wh[4] = {pk2(w0.z, w0.w), pk2(w1.z, w1.w),
                                        pk2(w2.z, w2.w), pk2(w3.z, w3.w)};
#pragma unroll
            for (int i = 0; i < 4; i++)
#pragma unroll
                for (int j = 0; j < 4; j++) {
                    fma2(acc2[i][j], al[i], wl[j]);
                    fma2(acc2[i][j], ah[i], wh[j]);
                }
        }
        __syncthreads();
    }

    float* dst = g_outp + (size_t)chunk * 65536;
#pragma unroll
    for (int i = 0; i < 4; i++) {
        int tk = ty * 4 + i;
#pragma unroll
        for (int j = 0; j < 4; j++)
            dst[tk * 1024 + o0 + tx * 4 + j] = up2sum(acc2[i][j]);
    }
}

// ---------------- K_oreduce: fixed-order reduce of outproj partials + bo ----------------
__global__ void __launch_bounds__(256) oreduce_kernel(const float* __restrict__ bo,
                                                      float4* __restrict__ out) {
    const int tok = blockIdx.x;
    const int b = tok >> 4, t = tok & 15;
    const int tid = threadIdx.x;
    float4 s = __ldg(&((const float4*)bo)[tid]);
    const float4* p = (const float4*)g_outp;
#pragma unroll
    for (int c = 0; c < 8; c++) {
        float4 v = p[(size_t)(c * 64 + tok) * 256 + tid];
        s.x += v.x; s.y += v.y; s.z += v.z; s.w += v.w;
    }
    out[(size_t)(b * 2048 + t) * 256 + tid] = s;
}

extern "C" void kernel_launch(void* const* d_in, const int* in_sizes, int n_in,
                              void* d_out, int out_size) {
    const float* x    = (const float*)d_in[0];
    const float* Wq   = (const float*)d_in[1];
    const float* bq   = (const float*)d_in[2];
    const float* Wk   = (const float*)d_in[3];
    const float* Wv   = (const float*)d_in[4];
    const float* bv   = (const float*)d_in[5];
    const float* Wo   = (const float*)d_in[6];
    const float* bo   = (const float*)d_in[7];
    const float* lna  = (const float*)d_in[8];
    const float* lnc  = (const float*)d_in[9];
    const float* lnd  = (const float*)d_in[10];
    const float* Wlq  = (const float*)d_in[11];
    const float* blq  = (const float*)d_in[12];
    const float* Wlk  = (const float*)d_in[13];
    const float* blk  = (const float*)d_in[14];
    const float* Wlv  = (const float*)d_in[15];
    const float* blv  = (const float*)d_in[16];
    const float* temp = (const float*)d_in[17];
    const float* thr  = (const float*)d_in[18];
    const float* fac  = (const float*)d_in[19];
    float* out = (float*)d_out;

    cudaFuncSetAttribute(iter01_kernel, cudaFuncAttributeMaxDynamicSharedMemorySize, SMEM_ITER_BYTES);
    cudaFuncSetAttribute(iter2_kernel, cudaFuncAttributeMaxDynamicSharedMemorySize, SMEM_ITER_BYTES);

    fillln_kernel<<<8192, 256>>>(bo, x, lna, (float4*)out);
    proj_kernel<<<dim3(16, 3, 8), 256>>>(Wq, Wk, Wv);
    iter01_kernel<<<64, 512, SMEM_ITER_BYTES>>>(Wlq, blq, Wlk, blk, Wlv, blv, lnc, lnd, temp, bq, bv);
    iter2_kernel<<<64, 512, SMEM_ITER_BYTES>>>(Wlq, blq, Wlk, blk, Wlv, blv, lnc, lnd, temp, thr, fac);
    outproj_kernel<<<dim3(16, 8), 256>>>(Wo);
    oreduce_kernel<<<64, 256>>>(bo, (float4*)out);
}

// round 12
// speedup vs baseline: 1.2410x; 1.2410x over previous
#include <cuda_runtime.h>
#include <math.h>

// B=4, T=2048, D=1024, H=16, HD=64, E=16 -> 64 active tokens total
#define SP  68   // iter tile stride (float4-aligned)
#define SPP 65   // GEMM tile stride

// ---------------- scratch ----------------
__device__ float g_xn[64 * 1024];          // LN(x), token-major [tok*1024 + o]
__device__ float g_qkvp[24 * 64 * 1024];   // qkv split-K partials [proj*8+chunk][tok*1024+o]
__device__ float g_outp[8 * 64 * 1024];    // outproj partials [chunk][tok*1024+o]
__device__ float g_aflat[64 * 1024];       // attn_out token-major [tok*1024 + h*64+d]
__device__ float g_diffpart[64];
__device__ unsigned int g_arrive = 0u;     // cross-block arrival counter (generation-based)

// smem layout for the fused iter kernel (floats)
#define WT_SZ   (64 * SP)
#define TILE_SZ (16 * SP)
#define OFF_WTQ 0
#define OFF_WTK (WT_SZ)
#define OFF_WTV (2 * WT_SZ)
#define OFF_QIN (3 * WT_SZ)
#define OFF_KIN (OFF_QIN + TILE_SZ)
#define OFF_VIN (OFF_KIN + TILE_SZ)
#define OFF_TQ  (OFF_VIN + TILE_SZ)
#define OFF_KLO (OFF_TQ + TILE_SZ)
#define OFF_VLO (OFF_KLO + TILE_SZ)
#define OFF_KSB (OFF_VLO + TILE_SZ)
#define OFF_PRB (OFF_KSB + TILE_SZ)
#define SMEM_ITER_FLOATS (OFF_PRB + 256)
#define SMEM_ITER_BYTES (SMEM_ITER_FLOATS * 4)

// ---------------- K_ln: LayerNorm over D=1024 for 64 active tokens ----------------
__global__ void __launch_bounds__(256) ln_kernel(const float* __restrict__ x,
                                                 const float* __restrict__ lna) {
    const int bt = blockIdx.x;            // tok = b*16+t
    const int b = bt >> 4, t = bt & 15;
    const int tid = threadIdx.x;
    const int wid = tid >> 5, lane = tid & 31;
    const float4* xr = (const float4*)(x + (size_t)(b * 2048 + t) * 1024);
    __shared__ float wp[8];
    __shared__ float stat[2];

    float4 v = __ldg(&xr[tid]);
    float s = (v.x + v.y) + (v.z + v.w);
#pragma unroll
    for (int o = 16; o > 0; o >>= 1) s += __shfl_xor_sync(0xffffffffu, s, o);
    if (lane == 0) wp[wid] = s;
    __syncthreads();
    if (tid == 0) {
        float m = 0.f;
#pragma unroll
        for (int i = 0; i < 8; i++) m += wp[i];
        stat[0] = m * (1.0f / 1024.0f);
    }
    __syncthreads();
    float m = stat[0];
    float dx = v.x - m, dy = v.y - m, dz = v.z - m, dw = v.w - m;
    float q = fmaf(dx, dx, dy * dy) + fmaf(dz, dz, dw * dw);
#pragma unroll
    for (int o = 16; o > 0; o >>= 1) q += __shfl_xor_sync(0xffffffffu, q, o);
    if (lane == 0) wp[wid] = q;
    __syncthreads();
    if (tid == 0) {
        float vv = 0.f;
#pragma unroll
        for (int i = 0; i < 8; i++) vv += wp[i];
        stat[1] = rsqrtf(vv * (1.0f / 1024.0f) + 1e-5f);
    }
    __syncthreads();
    float inv = stat[1];
    float4 w = __ldg(&((const float4*)lna)[tid]);
    float4 r;
    r.x = dx * inv * w.x; r.y = dy * inv * w.y;
    r.z = dz * inv * w.z; r.w = dw * inv * w.w;
    ((float4*)g_xn)[bt * 256 + tid] = r;
}

// ---------------- K_proj: split-K GEMM partials (scalar FFMA). grid (16,3,8) ----------------
__global__ void __launch_bounds__(256) proj_kernel(const float* __restrict__ Wq,
                                                   const float* __restrict__ Wk,
                                                   const float* __restrict__ Wv) {
    const int o0 = blockIdx.x * 64;
    const int proj = blockIdx.y;
    const int chunk = blockIdx.z;
    const float* W = (proj == 0) ? Wq : ((proj == 1) ? Wk : Wv);
    __shared__ float As[64][SPP];
    __shared__ float Ws[64][SPP];
    const int tid = threadIdx.x;
    const int tx = tid & 15, ty = tid >> 4;
    float acc[4][4];
#pragma unroll
    for (int i = 0; i < 4; i++)
#pragma unroll
        for (int j = 0; j < 4; j++) acc[i][j] = 0.f;

#pragma unroll
    for (int kt = 0; kt < 2; kt++) {
        int k0 = chunk * 128 + kt * 64;
#pragma unroll
        for (int l = tid; l < 4096; l += 256) {
            int r = l >> 6, c = l & 63;
            As[r][c] = g_xn[r * 1024 + k0 + c];
            Ws[r][c] = __ldg(&W[(size_t)(o0 + r) * 1024 + k0 + c]);
        }
        __syncthreads();
#pragma unroll 8
        for (int kk = 0; kk < 64; kk++) {
            float a[4], w[4];
#pragma unroll
            for (int i = 0; i < 4; i++) a[i] = As[ty * 4 + i][kk];
#pragma unroll
            for (int j = 0; j < 4; j++) w[j] = Ws[tx * 4 + j][kk];
#pragma unroll
            for (int i = 0; i < 4; i++)
#pragma unroll
                for (int j = 0; j < 4; j++) acc[i][j] = fmaf(a[i], w[j], acc[i][j]);
        }
        __syncthreads();
    }

    float* dst = g_qkvp + (size_t)(proj * 8 + chunk) * 65536;
#pragma unroll
    for (int i = 0; i < 4; i++) {
        int tk = ty * 4 + i;
#pragma unroll
        for (int j = 0; j < 4; j++)
            dst[tk * 1024 + o0 + tx * 4 + j] = acc[i][j];
    }
}

// ---------------- micro matmul: 128 threads, 8 outputs/thread (4 rows x 2 cols) ----------------
__device__ __forceinline__ void mm8(int tid_m, const float* Wt,
                                    const float* __restrict__ bias,
                                    const float* in, float* outb) {
    const int c = tid_m & 31;
    const int g = tid_m >> 5;   // 0..3 -> rows g, g+4, g+8, g+12
    const float4* r0 = (const float4*)(in + g * SP);
    const float4* r1 = (const float4*)(in + (g + 4) * SP);
    const float4* r2 = (const float4*)(in + (g + 8) * SP);
    const float4* r3 = (const float4*)(in + (g + 12) * SP);
    float acc[4][2];
#pragma unroll
    for (int i = 0; i < 4; i++) { acc[i][0] = 0.f; acc[i][1] = 0.f; }
#pragma unroll
    for (int jq = 0; jq < 16; jq++) {
        float4 x0 = r0[jq], x1 = r1[jq], x2 = r2[jq], x3 = r3[jq];
        float xv[4][4] = {{x0.x, x0.y, x0.z, x0.w}, {x1.x, x1.y, x1.z, x1.w},
                          {x2.x, x2.y, x2.z, x2.w}, {x3.x, x3.y, x3.z, x3.w}};
#pragma unroll
        for (int l = 0; l < 4; l++) {
            float wA = Wt[(jq * 4 + l) * SP + c];
            float wB = Wt[(jq * 4 + l) * SP + c + 32];
#pragma unroll
            for (int i = 0; i < 4; i++) {
                acc[i][0] = fmaf(xv[i][l], wA, acc[i][0]);
                acc[i][1] = fmaf(xv[i][l], wB, acc[i][1]);
            }
        }
    }
    float bA = __ldg(&bias[c]), bB = __ldg(&bias[c + 32]);
#pragma unroll
    for (int i = 0; i < 4; i++) {
        int row = g + 4 * i;
        outb[row * SP + c] = acc[i][0] + bA;
        outb[row * SP + c + 32] = acc[i][1] + bB;
    }
}

__device__ __forceinline__ void loadWt(const float* __restrict__ W, float* Wt, int tid) {
    for (int idx = tid; idx < 4096; idx += 512) {
        int d = idx >> 6, j = idx & 63;
        Wt[j * SP + d] = __ldg(&W[idx]);   // transposed: Wt[j][d]
    }
}

// One inner iteration for one (b,h): 512 threads. ai returned in registers.
__device__ __forceinline__ void small_iter512(int tid,
        const float* Wtq, const float* Wtk, const float* Wtv,
        const float* __restrict__ blq, const float* __restrict__ blk,
        const float* __restrict__ blv,
        const float* __restrict__ lnc, const float* __restrict__ lnd,
        float tscale,
        const float* qsrc, const float* ksrc, const float* vsrc,
        float* qd, float* kd, float* vd, float* ksb, float* probs,
        float& ai_lo, float& ai_hi) {
    // --- 3 concurrent micro-matmuls: warps 0-3 Q, 4-7 K, 8-11 V ---
    if (tid < 128)       mm8(tid,       Wtq, blq, qsrc, qd);
    else if (tid < 256)  mm8(tid - 128, Wtk, blk, ksrc, kd);
    else if (tid < 384)  mm8(tid - 256, Wtv, blv, vsrc, vd);
    __syncthreads();

    // --- LayerNorm(64): warps 0-7 -> q rows (in place), warps 8-15 -> k rows -> ksb ---
    {
        const int wid = tid >> 5, lane = tid & 31;
        const float* src = (wid < 8) ? qd : kd;
        float* dst = (wid < 8) ? qd : ksb;
        const float* lw = (wid < 8) ? lnc : lnd;
        const float sc = (wid < 8) ? tscale : 1.0f;
        const int row0 = (wid & 7) * 2;
#pragma unroll
        for (int rr = 0; rr < 2; rr++) {
            int row = row0 + rr;
            float v0 = src[row * SP + lane], v1 = src[row * SP + lane + 32];
            float s = v0 + v1;
#pragma unroll
            for (int o = 16; o > 0; o >>= 1) s += __shfl_xor_sync(0xffffffffu, s, o);
            float m = s * (1.0f / 64.0f);
            float d0 = v0 - m, d1 = v1 - m;
            float q = fmaf(d0, d0, d1 * d1);
#pragma unroll
            for (int o = 16; o > 0; o >>= 1) q += __shfl_xor_sync(0xffffffffu, q, o);
            float inv = rsqrtf(q * (1.0f / 64.0f) + 1e-5f) * sc;
            dst[row * SP + lane] = d0 * inv * __ldg(&lw[lane]);
            dst[row * SP + lane + 32] = d1 * inv * __ldg(&lw[lane + 32]);
        }
    }
    __syncthreads();

    // --- logits (16x16) * 1/8 ---
    if (tid < 256) {
        int t = tid >> 4, s_ = tid & 15;
        const float4* a4 = (const float4*)(qd + t * SP);
        const float4* k4 = (const float4*)(ksb + s_ * SP);
        float acc = 0.f;
#pragma unroll
        for (int jq = 0; jq < 16; jq++) {
            float4 a = a4[jq], k = k4[jq];
            acc = fmaf(a.x, k.x, acc); acc = fmaf(a.y, k.y, acc);
            acc = fmaf(a.z, k.z, acc); acc = fmaf(a.w, k.w, acc);
        }
        probs[tid] = acc * 0.125f;
    }
    __syncthreads();

    // --- softmax rows: one warp per row ---
    {
        const int wid = tid >> 5, lane = tid & 31;
        int s_ = lane & 15;
        float p = probs[wid * 16 + s_];
        float mx = p;
#pragma unroll
        for (int o = 8; o > 0; o >>= 1) mx = fmaxf(mx, __shfl_xor_sync(0xffffffffu, mx, o));
        float ex = __expf(p - mx);
        float sm = ex;
#pragma unroll
        for (int o = 8; o > 0; o >>= 1) sm += __shfl_xor_sync(0xffffffffu, sm, o);
        probs[wid * 16 + s_] = ex / sm;
    }
    __syncthreads();

    // --- ai = probs @ vl (2 outputs/thread, registers) ---
    {
        const int d = tid & 63, ts = tid >> 6;
        float a = 0.f, b = 0.f;
#pragma unroll
        for (int s_ = 0; s_ < 16; s_++) {
            float vv = vd[s_ * SP + d];
            a = fmaf(probs[ts * 16 + s_], vv, a);
            b = fmaf(probs[(ts + 8) * 16 + s_], vv, b);
        }
        ai_lo = a; ai_hi = b;
    }
    __syncthreads();
}

// ---------------- K_iter012: all 3 iterations fused, device-wide sync for diff ----------------
// 64 blocks x 512 threads, ~82KB smem -> 1 block/SM, 64 < 148 SMs: whole grid
// co-resident in wave 1, so the arrival-counter spin cannot deadlock.
__global__ void __launch_bounds__(512) iter012_kernel(
        const float* __restrict__ Wlq, const float* __restrict__ blq,
        const float* __restrict__ Wlk, const float* __restrict__ blk,
        const float* __restrict__ Wlv, const float* __restrict__ blv,
        const float* __restrict__ lnc, const float* __restrict__ lnd,
        const float* __restrict__ temp,
        const float* __restrict__ bq, const float* __restrict__ bv,
        const float* __restrict__ thrp, const float* __restrict__ facp) {
    extern __shared__ float smx[];
    float* Wtq = smx + OFF_WTQ; float* Wtk = smx + OFF_WTK; float* Wtv = smx + OFF_WTV;
    float* qin = smx + OFF_QIN; float* kin = smx + OFF_KIN; float* vin = smx + OFF_VIN;
    float* tqb = smx + OFF_TQ;  float* klo = smx + OFF_KLO; float* vlo = smx + OFF_VLO;
    float* ksb = smx + OFF_KSB; float* probs = smx + OFF_PRB;
    const int bx = blockIdx.x, tid = threadIdx.x;
    const int b = bx >> 4, h = bx & 15;

    loadWt(Wlq, Wtq, tid);
    loadWt(Wlk, Wtk, tid);
    loadWt(Wlv, Wtv, tid);

    // reduce qkv split-K partials (fixed order), apply scale/bias
    const float SC = 0.35355339059327373f;   // 64^-0.25
    for (int e = tid; e < 1024; e += 512) {
        int t = e >> 6, dd = e & 63;
        int o = h * 64 + dd;
        int g = (b * 16 + t) * 1024 + o;
        float qv = 0.f, kv = 0.f, vv = 0.f;
#pragma unroll
        for (int c = 0; c < 8; c++) {
            qv += __ldg(&g_qkvp[(size_t)c * 65536 + g]);
            kv += __ldg(&g_qkvp[(size_t)(8 + c) * 65536 + g]);
            vv += __ldg(&g_qkvp[(size_t)(16 + c) * 65536 + g]);
        }
        qin[t * SP + dd] = (qv + __ldg(&bq[o])) * SC;
        kin[t * SP + dd] = kv * SC;
        vin[t * SP + dd] = vv + __ldg(&bv[o]);
    }
    __syncthreads();

    const int d = tid & 63, ts = tid >> 6;
    const float temp0 = __ldg(temp);

    // --- iteration 0 ---
    float t0 = temp0;
    float ts0 = (t0 != 1.0f && t0 > 0.0f) ? rsqrtf(t0) : 1.0f;
    float ai0_lo, ai0_hi;
    small_iter512(tid, Wtq, Wtk, Wtv, blq, blk, blv, lnc, lnd, ts0,
                  qin, kin, vin, tqb, klo, vlo, ksb, probs, ai0_lo, ai0_hi);

    qin[ts * SP + d] += ai0_lo;
    qin[(ts + 8) * SP + d] += ai0_hi;
    __syncthreads();

    // --- iteration 1 (inputs: qin, kl0=klo, vl0=vlo; outputs kl1->kin, vl1->vin) ---
    float t1 = temp0 + 0.005f;
    float ts1 = (t1 != 1.0f && t1 > 0.0f) ? rsqrtf(t1) : 1.0f;
    float ai1_lo, ai1_hi;
    small_iter512(tid, Wtq, Wtk, Wtv, blq, blk, blv, lnc, lnd, ts1,
                  qin, klo, vlo, tqb, kin, vin, ksb, probs, ai1_lo, ai1_hi);

    // --- block partial of sum|ai1 - ai0| ---
    float psum = fabsf(ai1_lo - ai0_lo) + fabsf(ai1_hi - ai0_hi);
#pragma unroll
    for (int o = 16; o > 0; o >>= 1) psum += __shfl_xor_sync(0xffffffffu, psum, o);
    const int wid = tid >> 5, lane = tid & 31;
    if (lane == 0) probs[wid] = psum;
    __syncthreads();

    // --- device-wide barrier + deterministic fixed-order global diff ---
    if (tid == 0) {
        float s = 0.f;
#pragma unroll
        for (int i = 0; i < 16; i++) s += probs[i];   // fixed order
        g_diffpart[bx] = s;
        __threadfence();
        unsigned int old = atomicAdd(&g_arrive, 1u);
        unsigned int target = ((old >> 6) + 1u) << 6;   // generation end
        while (*((volatile unsigned int*)&g_arrive) < target) { }
        __threadfence();
        float tot = 0.f;
#pragma unroll
        for (int i = 0; i < 64; i++) tot += ((volatile float*)g_diffpart)[i]; // fixed order
        float diff = tot * (1.0f / 8388608.0f);        // mean over B*H*T*hd
        float th = __ldg(thrp), fa = __ldg(facp);
        probs[64] = (diff < th + fa * diff) ? 1.0f : 0.0f;
    }
    __syncthreads();
    bool done = (probs[64] != 0.0f);

    if (done) {
        g_aflat[(b * 16 + ts) * 1024 + h * 64 + d] = ai1_lo;
        g_aflat[(b * 16 + ts + 8) * 1024 + h * 64 + d] = ai1_hi;
        return;
    }

    // --- iteration 2 (inputs: qin+=ai1, kl1=kin, vl1=vin) ---
    qin[ts * SP + d] += ai1_lo;
    qin[(ts + 8) * SP + d] += ai1_hi;
    __syncthreads();

    float t2 = temp0 + 0.01f;
    float ts2 = (t2 != 1.0f && t2 > 0.0f) ? rsqrtf(t2) : 1.0f;
    float ai2_lo, ai2_hi;
    small_iter512(tid, Wtq, Wtk, Wtv, blq, blk, blv, lnc, lnd, ts2,
                  qin, kin, vin, tqb, klo, vlo, ksb, probs, ai2_lo, ai2_hi);

    g_aflat[(b * 16 + ts) * 1024 + h * 64 + d] = ai2_lo;
    g_aflat[(b * 16 + ts + 8) * 1024 + h * 64 + d] = ai2_hi;
}

// ---------------- K_outproj: split-K partials (scalar FFMA). grid (16,8) ----------------
__global__ void __launch_bounds__(256) outproj_kernel(const float* __restrict__ Wo) {
    const int o0 = blockIdx.x * 64;
    const int chunk = blockIdx.y;
    __shared__ float As[64][SPP];
    __shared__ float Ws[64][SPP];
    const int tid = threadIdx.x;
    const int tx = tid & 15, ty = tid >> 4;
    float acc[4][4];
#pragma unroll
    for (int i = 0; i < 4; i++)
#pragma unroll
        for (int j = 0; j < 4; j++) acc[i][j] = 0.f;

#pragma unroll
    for (int kt = 0; kt < 2; kt++) {
        int k0 = chunk * 128 + kt * 64;
#pragma unroll
        for (int l = tid; l < 4096; l += 256) {
            int r = l >> 6, c = l & 63;
            As[r][c] = g_aflat[r * 1024 + k0 + c];
            Ws[r][c] = __ldg(&Wo[(size_t)(o0 + r) * 1024 + k0 + c]);
        }
        __syncthreads();
#pragma unroll 8
        for (int kk = 0; kk < 64; kk++) {
            float a[4], w[4];
#pragma unroll
            for (int i = 0; i < 4; i++) a[i] = As[ty * 4 + i][kk];
#pragma unroll
            for (int j = 0; j < 4; j++) w[j] = Ws[tx * 4 + j][kk];
#pragma unroll
            for (int i = 0; i < 4; i++)
#pragma unroll
                for (int j = 0; j < 4; j++) acc[i][j] = fmaf(a[i], w[j], acc[i][j]);
        }
        __syncthreads();
    }

    float* dst = g_outp + (size_t)chunk * 65536;
#pragma unroll
    for (int i = 0; i < 4; i++) {
        int tk = ty * 4 + i;
#pragma unroll
        for (int j = 0; j < 4; j++)
            dst[tk * 1024 + o0 + tx * 4 + j] = acc[i][j];
    }
}

// ---------------- K_finalize: whole output. t<16: reduce partials + bo; else bo ----------------
__global__ void __launch_bounds__(256) finalize_kernel(const float* __restrict__ bo,
                                                       float4* __restrict__ out) {
    const int row = blockIdx.x;              // b*2048 + t
    const int t = row & 2047;
    const int tid = threadIdx.x;
    float4 s = __ldg(&((const float4*)bo)[tid]);
    if (t < 16) {
        const int b = row >> 11;
        const int tok = b * 16 + t;
        const float4* p = (const float4*)g_outp;
#pragma unroll
        for (int c = 0; c < 8; c++) {
            float4 v = p[(size_t)(c * 64 + tok) * 256 + tid];
            s.x += v.x; s.y += v.y; s.z += v.z; s.w += v.w;
        }
    }
    out[(size_t)row * 256 + tid] = s;
}

extern "C" void kernel_launch(void* const* d_in, const int* in_sizes, int n_in,
                              void* d_out, int out_size) {
    const float* x    = (const float*)d_in[0];
    const float* Wq   = (const float*)d_in[1];
    const float* bq   = (const float*)d_in[2];
    const float* Wk   = (const float*)d_in[3];
    const float* Wv   = (const float*)d_in[4];
    const float* bv   = (const float*)d_in[5];
    const float* Wo   = (const float*)d_in[6];
    const float* bo   = (const float*)d_in[7];
    const float* lna  = (const float*)d_in[8];
    const float* lnc  = (const float*)d_in[9];
    const float* lnd  = (const float*)d_in[10];
    const float* Wlq  = (const float*)d_in[11];
    const float* blq  = (const float*)d_in[12];
    const float* Wlk  = (const float*)d_in[13];
    const float* blk  = (const float*)d_in[14];
    const float* Wlv  = (const float*)d_in[15];
    const float* blv  = (const float*)d_in[16];
    const float* temp = (const float*)d_in[17];
    const float* thr  = (const float*)d_in[18];
    const float* fac  = (const float*)d_in[19];
    float* out = (float*)d_out;

    cudaFuncSetAttribute(iter012_kernel, cudaFuncAttributeMaxDynamicSharedMemorySize,
                         SMEM_ITER_BYTES);

    ln_kernel<<<64, 256>>>(x, lna);
    proj_kernel<<<dim3(16, 3, 8), 256>>>(Wq, Wk, Wv);
    iter012_kernel<<<64, 512, SMEM_ITER_BYTES>>>(Wlq, blq, Wlk, blk, Wlv, blv,
                                                 lnc, lnd, temp, bq, bv, thr, fac);
    outproj_kernel<<<dim3(16, 8), 256>>>(Wo);
    finalize_kernel<<<8192, 256>>>(bo, (float4*)out);
}

// round 13
// speedup vs baseline: 1.4771x; 1.1902x over previous
#include <cuda_runtime.h>
#include <math.h>

// B=4, T=2048, D=1024, H=16, HD=64, E=16 -> 64 active tokens total
#define SP  68   // iter tile stride (float4-aligned)
#define SPP 65   // GEMM tile stride (odd -> conflict-free with strided col map)

// ---------------- scratch ----------------
__device__ float g_mean[64];               // per-token LN stats
__device__ float g_rstd[64];
__device__ float g_qkvp[24 * 64 * 1024];   // qkv split-K partials [proj*8+chunk][tok*1024+o]
__device__ float g_outp[16 * 64 * 1024];   // outproj partials [chunk][tok*1024+o]
__device__ float g_aflat[64 * 1024];       // attn_out token-major [tok*1024 + h*64+d]
__device__ float g_diffpart[64];
__device__ unsigned int g_arrive = 0u;     // iter012 arrival counter (generation-based)
__device__ unsigned int g_arrive2 = 0u;    // outproj arrival counter (generation-based)

// smem layout for the fused iter kernel (floats)
#define WT_SZ   (64 * SP)
#define TILE_SZ (16 * SP)
#define OFF_WTQ 0
#define OFF_WTK (WT_SZ)
#define OFF_WTV (2 * WT_SZ)
#define OFF_QIN (3 * WT_SZ)
#define OFF_KIN (OFF_QIN + TILE_SZ)
#define OFF_VIN (OFF_KIN + TILE_SZ)
#define OFF_TQ  (OFF_VIN + TILE_SZ)
#define OFF_KLO (OFF_TQ + TILE_SZ)
#define OFF_VLO (OFF_KLO + TILE_SZ)
#define OFF_KSB (OFF_VLO + TILE_SZ)
#define OFF_PRB (OFF_KSB + TILE_SZ)
#define SMEM_ITER_FLOATS (OFF_PRB + 256)
#define SMEM_ITER_BYTES (SMEM_ITER_FLOATS * 4)

// ---------------- K_fillstats: out=bo everywhere; blocks<64 also compute LN stats ----------------
__global__ void __launch_bounds__(256) fillstats_kernel(const float* __restrict__ bo,
                                                        const float* __restrict__ x,
                                                        float4* __restrict__ out) {
    const int tid = threadIdx.x;
    const int bidx = blockIdx.x;
    out[bidx * 256 + tid] = __ldg(&((const float4*)bo)[tid]);

    if (bidx < 64) {
        const int b = bidx >> 4, t = bidx & 15;
        const int wid = tid >> 5, lane = tid & 31;
        const float4* xr = (const float4*)(x + (size_t)(b * 2048 + t) * 1024);
        __shared__ float wp[8];
        __shared__ float sm;

        float4 v = __ldg(&xr[tid]);
        float s = (v.x + v.y) + (v.z + v.w);
#pragma unroll
        for (int o = 16; o > 0; o >>= 1) s += __shfl_xor_sync(0xffffffffu, s, o);
        if (lane == 0) wp[wid] = s;
        __syncthreads();
        if (tid == 0) {
            float m = 0.f;
#pragma unroll
            for (int i = 0; i < 8; i++) m += wp[i];
            sm = m * (1.0f / 1024.0f);
        }
        __syncthreads();
        float m = sm;
        float dx = v.x - m, dy = v.y - m, dz = v.z - m, dw = v.w - m;
        float q = fmaf(dx, dx, dy * dy) + fmaf(dz, dz, dw * dw);
#pragma unroll
        for (int o = 16; o > 0; o >>= 1) q += __shfl_xor_sync(0xffffffffu, q, o);
        if (lane == 0) wp[wid] = q;
        __syncthreads();
        if (tid == 0) {
            float vv = 0.f;
#pragma unroll
            for (int i = 0; i < 8; i++) vv += wp[i];
            g_mean[bidx] = m;
            g_rstd[bidx] = rsqrtf(vv * (1.0f / 1024.0f) + 1e-5f);
        }
    }
}

// ---------------- K_proj: split-K GEMM partials, LN applied on the fly. grid (16,3,8) ----------------
__global__ void __launch_bounds__(256) proj_kernel(const float* __restrict__ x,
                                                   const float* __restrict__ lna,
                                                   const float* __restrict__ Wq,
                                                   const float* __restrict__ Wk,
                                                   const float* __restrict__ Wv) {
    const int o0 = blockIdx.x * 64;
    const int proj = blockIdx.y;
    const int chunk = blockIdx.z;
    const float* W = (proj == 0) ? Wq : ((proj == 1) ? Wk : Wv);
    __shared__ float As[64][SPP];
    __shared__ float Ws[64][SPP];
    __shared__ float mrow[64], irow[64];
    const int tid = threadIdx.x;
    const int tx = tid & 15, ty = tid >> 4;
    if (tid < 64) { mrow[tid] = g_mean[tid]; irow[tid] = g_rstd[tid]; }
    float acc[4][4];
#pragma unroll
    for (int i = 0; i < 4; i++)
#pragma unroll
        for (int j = 0; j < 4; j++) acc[i][j] = 0.f;
    __syncthreads();

#pragma unroll
    for (int kt = 0; kt < 2; kt++) {
        int k0 = chunk * 128 + kt * 64;
#pragma unroll
        for (int l = tid; l < 4096; l += 256) {
            int r = l >> 6, c = l & 63;
            int bb = r >> 4, tt = r & 15;
            float xv = __ldg(&x[(size_t)(bb * 2048 + tt) * 1024 + k0 + c]);
            As[r][c] = (xv - mrow[r]) * irow[r] * __ldg(&lna[k0 + c]);
            Ws[r][c] = __ldg(&W[(size_t)(o0 + r) * 1024 + k0 + c]);
        }
        __syncthreads();
#pragma unroll 8
        for (int kk = 0; kk < 64; kk++) {
            float a[4], w[4];
#pragma unroll
            for (int i = 0; i < 4; i++) a[i] = As[ty * 4 + i][kk];
#pragma unroll
            for (int j = 0; j < 4; j++) w[j] = Ws[tx + 16 * j][kk];   // conflict-free
#pragma unroll
            for (int i = 0; i < 4; i++)
#pragma unroll
                for (int j = 0; j < 4; j++) acc[i][j] = fmaf(a[i], w[j], acc[i][j]);
        }
        __syncthreads();
    }

    float* dst = g_qkvp + (size_t)(proj * 8 + chunk) * 65536;
#pragma unroll
    for (int i = 0; i < 4; i++) {
        int tk = ty * 4 + i;
#pragma unroll
        for (int j = 0; j < 4; j++)
            dst[tk * 1024 + o0 + tx + 16 * j] = acc[i][j];
    }
}

// ---------------- micro matmul: 128 threads, 8 outputs/thread (4 rows x 2 cols) ----------------
__device__ __forceinline__ void mm8(int tid_m, const float* Wt,
                                    const float* __restrict__ bias,
                                    const float* in, float* outb) {
    const int c = tid_m & 31;
    const int g = tid_m >> 5;   // 0..3 -> rows g, g+4, g+8, g+12
    const float4* r0 = (const float4*)(in + g * SP);
    const float4* r1 = (const float4*)(in + (g + 4) * SP);
    const float4* r2 = (const float4*)(in + (g + 8) * SP);
    const float4* r3 = (const float4*)(in + (g + 12) * SP);
    float acc[4][2];
#pragma unroll
    for (int i = 0; i < 4; i++) { acc[i][0] = 0.f; acc[i][1] = 0.f; }
#pragma unroll
    for (int jq = 0; jq < 16; jq++) {
        float4 x0 = r0[jq], x1 = r1[jq], x2 = r2[jq], x3 = r3[jq];
        float xv[4][4] = {{x0.x, x0.y, x0.z, x0.w}, {x1.x, x1.y, x1.z, x1.w},
                          {x2.x, x2.y, x2.z, x2.w}, {x3.x, x3.y, x3.z, x3.w}};
#pragma unroll
        for (int l = 0; l < 4; l++) {
            float wA = Wt[(jq * 4 + l) * SP + c];
            float wB = Wt[(jq * 4 + l) * SP + c + 32];
#pragma unroll
            for (int i = 0; i < 4; i++) {
                acc[i][0] = fmaf(xv[i][l], wA, acc[i][0]);
                acc[i][1] = fmaf(xv[i][l], wB, acc[i][1]);
            }
        }
    }
    float bA = __ldg(&bias[c]), bB = __ldg(&bias[c + 32]);
#pragma unroll
    for (int i = 0; i < 4; i++) {
        int row = g + 4 * i;
        outb[row * SP + c] = acc[i][0] + bA;
        outb[row * SP + c + 32] = acc[i][1] + bB;
    }
}

__device__ __forceinline__ void loadWt(const float* __restrict__ W, float* Wt, int tid) {
    for (int idx = tid; idx < 4096; idx += 512) {
        int d = idx >> 6, j = idx & 63;
        Wt[j * SP + d] = __ldg(&W[idx]);   // transposed: Wt[j][d]
    }
}

// One inner iteration for one (b,h): 512 threads. ai returned in registers.
__device__ __forceinline__ void small_iter512(int tid,
        const float* Wtq, const float* Wtk, const float* Wtv,
        const float* __restrict__ blq, const float* __restrict__ blk,
        const float* __restrict__ blv,
        const float* __restrict__ lnc, const float* __restrict__ lnd,
        float tscale,
        const float* qsrc, const float* ksrc, const float* vsrc,
        float* qd, float* kd, float* vd, float* ksb, float* probs,
        float& ai_lo, float& ai_hi) {
    // --- 3 concurrent micro-matmuls: warps 0-3 Q, 4-7 K, 8-11 V ---
    if (tid < 128)       mm8(tid,       Wtq, blq, qsrc, qd);
    else if (tid < 256)  mm8(tid - 128, Wtk, blk, ksrc, kd);
    else if (tid < 384)  mm8(tid - 256, Wtv, blv, vsrc, vd);
    __syncthreads();

    // --- LayerNorm(64): warps 0-7 -> q rows (in place), warps 8-15 -> k rows -> ksb ---
    {
        const int wid = tid >> 5, lane = tid & 31;
        const float* src = (wid < 8) ? qd : kd;
        float* dst = (wid < 8) ? qd : ksb;
        const float* lw = (wid < 8) ? lnc : lnd;
        const float sc = (wid < 8) ? tscale : 1.0f;
        const int row0 = (wid & 7) * 2;
#pragma unroll
        for (int rr = 0; rr < 2; rr++) {
            int row = row0 + rr;
            float v0 = src[row * SP + lane], v1 = src[row * SP + lane + 32];
            float s = v0 + v1;
#pragma unroll
            for (int o = 16; o > 0; o >>= 1) s += __shfl_xor_sync(0xffffffffu, s, o);
            float m = s * (1.0f / 64.0f);
            float d0 = v0 - m, d1 = v1 - m;
            float q = fmaf(d0, d0, d1 * d1);
#pragma unroll
            for (int o = 16; o > 0; o >>= 1) q += __shfl_xor_sync(0xffffffffu, q, o);
            float inv = rsqrtf(q * (1.0f / 64.0f) + 1e-5f) * sc;
            dst[row * SP + lane] = d0 * inv * __ldg(&lw[lane]);
            dst[row * SP + lane + 32] = d1 * inv * __ldg(&lw[lane + 32]);
        }
    }
    __syncthreads();

    // --- logits (16x16) * 1/8 ---
    if (tid < 256) {
        int t = tid >> 4, s_ = tid & 15;
        const float4* a4 = (const float4*)(qd + t * SP);
        const float4* k4 = (const float4*)(ksb + s_ * SP);
        float acc = 0.f;
#pragma unroll
        for (int jq = 0; jq < 16; jq++) {
            float4 a = a4[jq], k = k4[jq];
            acc = fmaf(a.x, k.x, acc); acc = fmaf(a.y, k.y, acc);
            acc = fmaf(a.z, k.z, acc); acc = fmaf(a.w, k.w, acc);
        }
        probs[tid] = acc * 0.125f;
    }
    __syncthreads();

    // --- softmax rows: one warp per row ---
    {
        const int wid = tid >> 5, lane = tid & 31;
        int s_ = lane & 15;
        float p = probs[wid * 16 + s_];
        float mx = p;
#pragma unroll
        for (int o = 8; o > 0; o >>= 1) mx = fmaxf(mx, __shfl_xor_sync(0xffffffffu, mx, o));
        float ex = __expf(p - mx);
        float sm = ex;
#pragma unroll
        for (int o = 8; o > 0; o >>= 1) sm += __shfl_xor_sync(0xffffffffu, sm, o);
        probs[wid * 16 + s_] = ex / sm;
    }
    __syncthreads();

    // --- ai = probs @ vl (2 outputs/thread, registers) ---
    {
        const int d = tid & 63, ts = tid >> 6;
        float a = 0.f, b = 0.f;
#pragma unroll
        for (int s_ = 0; s_ < 16; s_++) {
            float vv = vd[s_ * SP + d];
            a = fmaf(probs[ts * 16 + s_], vv, a);
            b = fmaf(probs[(ts + 8) * 16 + s_], vv, b);
        }
        ai_lo = a; ai_hi = b;
    }
    __syncthreads();
}

// ---------------- K_iter012: all 3 iterations fused, device-wide sync for diff ----------------
__global__ void __launch_bounds__(512) iter012_kernel(
        const float* __restrict__ Wlq, const float* __restrict__ blq,
        const float* __restrict__ Wlk, const float* __restrict__ blk,
        const float* __restrict__ Wlv, const float* __restrict__ blv,
        const float* __restrict__ lnc, const float* __restrict__ lnd,
        const float* __restrict__ temp,
        const float* __restrict__ bq, const float* __restrict__ bv,
        const float* __restrict__ thrp, const float* __restrict__ facp) {
    extern __shared__ float smx[];
    float* Wtq = smx + OFF_WTQ; float* Wtk = smx + OFF_WTK; float* Wtv = smx + OFF_WTV;
    float* qin = smx + OFF_QIN; float* kin = smx + OFF_KIN; float* vin = smx + OFF_VIN;
    float* tqb = smx + OFF_TQ;  float* klo = smx + OFF_KLO; float* vlo = smx + OFF_VLO;
    float* ksb = smx + OFF_KSB; float* probs = smx + OFF_PRB;
    const int bx = blockIdx.x, tid = threadIdx.x;
    const int b = bx >> 4, h = bx & 15;

    loadWt(Wlq, Wtq, tid);
    loadWt(Wlk, Wtk, tid);
    loadWt(Wlv, Wtv, tid);

    // reduce qkv split-K partials (fixed order), apply scale/bias
    const float SC = 0.35355339059327373f;   // 64^-0.25
    for (int e = tid; e < 1024; e += 512) {
        int t = e >> 6, dd = e & 63;
        int o = h * 64 + dd;
        int g = (b * 16 + t) * 1024 + o;
        float qv = 0.f, kv = 0.f, vv = 0.f;
#pragma unroll
        for (int c = 0; c < 8; c++) {
            qv += __ldg(&g_qkvp[(size_t)c * 65536 + g]);
            kv += __ldg(&g_qkvp[(size_t)(8 + c) * 65536 + g]);
            vv += __ldg(&g_qkvp[(size_t)(16 + c) * 65536 + g]);
        }
        qin[t * SP + dd] = (qv + __ldg(&bq[o])) * SC;
        kin[t * SP + dd] = kv * SC;
        vin[t * SP + dd] = vv + __ldg(&bv[o]);
    }
    __syncthreads();

    const int d = tid & 63, ts = tid >> 6;
    const float temp0 = __ldg(temp);

    // --- iteration 0 ---
    float t0 = temp0;
    float ts0 = (t0 != 1.0f && t0 > 0.0f) ? rsqrtf(t0) : 1.0f;
    float ai0_lo, ai0_hi;
    small_iter512(tid, Wtq, Wtk, Wtv, blq, blk, blv, lnc, lnd, ts0,
                  qin, kin, vin, tqb, klo, vlo, ksb, probs, ai0_lo, ai0_hi);

    qin[ts * SP + d] += ai0_lo;
    qin[(ts + 8) * SP + d] += ai0_hi;
    __syncthreads();

    // --- iteration 1 (inputs: qin, kl0=klo, vl0=vlo; outputs kl1->kin, vl1->vin) ---
    float t1 = temp0 + 0.005f;
    float ts1 = (t1 != 1.0f && t1 > 0.0f) ? rsqrtf(t1) : 1.0f;
    float ai1_lo, ai1_hi;
    small_iter512(tid, Wtq, Wtk, Wtv, blq, blk, blv, lnc, lnd, ts1,
                  qin, klo, vlo, tqb, kin, vin, ksb, probs, ai1_lo, ai1_hi);

    // --- block partial of sum|ai1 - ai0| ---
    float psum = fabsf(ai1_lo - ai0_lo) + fabsf(ai1_hi - ai0_hi);
#pragma unroll
    for (int o = 16; o > 0; o >>= 1) psum += __shfl_xor_sync(0xffffffffu, psum, o);
    const int wid = tid >> 5, lane = tid & 31;
    if (lane == 0) probs[wid] = psum;
    __syncthreads();

    // --- device-wide barrier + deterministic fixed-order global diff ---
    if (tid == 0) {
        float s = 0.f;
#pragma unroll
        for (int i = 0; i < 16; i++) s += probs[i];   // fixed order
        g_diffpart[bx] = s;
        __threadfence();
        unsigned int old = atomicAdd(&g_arrive, 1u);
        unsigned int target = ((old >> 6) + 1u) << 6;   // generation end
        while (*((volatile unsigned int*)&g_arrive) < target) { }
        __threadfence();
        float tot = 0.f;
#pragma unroll
        for (int i = 0; i < 64; i++) tot += ((volatile float*)g_diffpart)[i]; // fixed order
        float diff = tot * (1.0f / 8388608.0f);        // mean over B*H*T*hd
        float th = __ldg(thrp), fa = __ldg(facp);
        probs[64] = (diff < th + fa * diff) ? 1.0f : 0.0f;
    }
    __syncthreads();
    bool done = (probs[64] != 0.0f);

    if (done) {
        g_aflat[(b * 16 + ts) * 1024 + h * 64 + d] = ai1_lo;
        g_aflat[(b * 16 + ts + 8) * 1024 + h * 64 + d] = ai1_hi;
        return;
    }

    // --- iteration 2 (inputs: qin+=ai1, kl1=kin, vl1=vin) ---
    qin[ts * SP + d] += ai1_lo;
    qin[(ts + 8) * SP + d] += ai1_hi;
    __syncthreads();

    float t2 = temp0 + 0.01f;
    float ts2 = (t2 != 1.0f && t2 > 0.0f) ? rsqrtf(t2) : 1.0f;
    float ai2_lo, ai2_hi;
    small_iter512(tid, Wtq, Wtk, Wtv, blq, blk, blv, lnc, lnd, ts2,
                  qin, kin, vin, tqb, klo, vlo, ksb, probs, ai2_lo, ai2_hi);

    g_aflat[(b * 16 + ts) * 1024 + h * 64 + d] = ai2_lo;
    g_aflat[(b * 16 + ts + 8) * 1024 + h * 64 + d] = ai2_hi;
}

// ---------------- K_outproj: split-K 16 partials + fused device-barrier reduce ----------------
// grid (16 otiles, 16 kchunks) = 256 blocks, ~6 co-resident blocks/SM -> barrier safe.
__global__ void __launch_bounds__(256) outproj_kernel(const float* __restrict__ Wo,
                                                      const float* __restrict__ bo,
                                                      float4* __restrict__ out) {
    const int o0 = blockIdx.x * 64;
    const int chunk = blockIdx.y;
    const int flat = blockIdx.y * 16 + blockIdx.x;
    __shared__ float As[64][SPP];
    __shared__ float Ws[64][SPP];
    const int tid = threadIdx.x;
    const int tx = tid & 15, ty = tid >> 4;
    float acc[4][4];
#pragma unroll
    for (int i = 0; i < 4; i++)
#pragma unroll
        for (int j = 0; j < 4; j++) acc[i][j] = 0.f;

    const int k0 = chunk * 64;
#pragma unroll
    for (int l = tid; l < 4096; l += 256) {
        int r = l >> 6, c = l & 63;
        As[r][c] = g_aflat[r * 1024 + k0 + c];
        Ws[r][c] = __ldg(&Wo[(size_t)(o0 + r) * 1024 + k0 + c]);
    }
    __syncthreads();
#pragma unroll 8
    for (int kk = 0; kk < 64; kk++) {
        float a[4], w[4];
#pragma unroll
        for (int i = 0; i < 4; i++) a[i] = As[ty * 4 + i][kk];
#pragma unroll
        for (int j = 0; j < 4; j++) w[j] = Ws[tx + 16 * j][kk];   // conflict-free
#pragma unroll
        for (int i = 0; i < 4; i++)
#pragma unroll
            for (int j = 0; j < 4; j++) acc[i][j] = fmaf(a[i], w[j], acc[i][j]);
    }

    float* dst = g_outp + (size_t)chunk * 65536;
#pragma unroll
    for (int i = 0; i < 4; i++) {
        int tk = ty * 4 + i;
#pragma unroll
        for (int j = 0; j < 4; j++)
            dst[tk * 1024 + o0 + tx + 16 * j] = acc[i][j];
    }

    // --- device-wide barrier, then blocks 0..63 write final t<16 rows ---
    __threadfence();
    __syncthreads();
    if (tid == 0) {
        unsigned int old = atomicAdd(&g_arrive2, 1u);
        if (flat < 64) {
            unsigned int target = ((old >> 8) + 1u) << 8;   // generation of 256
            while (*((volatile unsigned int*)&g_arrive2) < target) { }
        }
    }
    if (flat >= 64) return;
    __syncthreads();
    __threadfence();

    const int tok = flat;
    const int b = tok >> 4, t = tok & 15;
    float4 s = __ldg(&((const float4*)bo)[tid]);
    const float4* p = (const float4*)g_outp;
#pragma unroll
    for (int c = 0; c < 16; c++) {
        float4 v = __ldcg(&p[(size_t)(c * 16384) + tok * 256 + tid]);
        s.x += v.x; s.y += v.y; s.z += v.z; s.w += v.w;
    }
    out[(size_t)(b * 2048 + t) * 256 + tid] = s;
}

extern "C" void kernel_launch(void* const* d_in, const int* in_sizes, int n_in,
                              void* d_out, int out_size) {
    const float* x    = (const float*)d_in[0];
    const float* Wq   = (const float*)d_in[1];
    const float* bq   = (const float*)d_in[2];
    const float* Wk   = (const float*)d_in[3];
    const float* Wv   = (const float*)d_in[4];
    const float* bv   = (const float*)d_in[5];
    const float* Wo   = (const float*)d_in[6];
    const float* bo   = (const float*)d_in[7];
    const float* lna  = (const float*)d_in[8];
    const float* lnc  = (const float*)d_in[9];
    const float* lnd  = (const float*)d_in[10];
    const float* Wlq  = (const float*)d_in[11];
    const float* blq  = (const float*)d_in[12];
    const float* Wlk  = (const float*)d_in[13];
    const float* blk  = (const float*)d_in[14];
    const float* Wlv  = (const float*)d_in[15];
    const float* blv  = (const float*)d_in[16];
    const float* temp = (const float*)d_in[17];
    const float* thr  = (const float*)d_in[18];
    const float* fac  = (const float*)d_in[19];
    float* out = (float*)d_out;

    cudaFuncSetAttribute(iter012_kernel, cudaFuncAttributeMaxDynamicSharedMemorySize,
                         SMEM_ITER_BYTES);

    fillstats_kernel<<<8192, 256>>>(bo, x, (float4*)out);   // bo fill + LN stats
    proj_kernel<<<dim3(16, 3, 8), 256>>>(x, lna, Wq, Wk, Wv);
    iter012_kernel<<<64, 512, SMEM_ITER_BYTES>>>(Wlq, blq, Wlk, blk, Wlv, blv,
                                                 lnc, lnd, temp, bq, bv, thr, fac);
    outproj_kernel<<<dim3(16, 16), 256>>>(Wo, bo, (float4*)out);
}